// round 6
// baseline (speedup 1.0000x reference)
#include <cuda_runtime.h>
#include <cuda_bf16.h>
#include <math.h>
#include <cstdint>

#define I_ 16
#define T_ 64
#define Q_ 196
#define K_ 32
#define E_ 512
#define H_ 8
#define D_ 64

#define OUT_N   (I_*T_*E_)                  // 524288
#define ATT_N   (I_*T_*H_*Q_*K_)            // 51380224
#define SCALE_  0.044194173824159216f       // 1/sqrt(512)
#define LOG2E_  1.4426950408889634f
#define SC2_    (SCALE_*LOG2E_)

#define SA_  200                            // A/B smem stride (bf16 elems), padded
#define MR_  208                            // A rows (196 padded to 13*16)
#define EST_ 36                             // sE row stride (floats)

#define ABYTES   (MR_*SA_*2)                // 83200 (also holds sE: 208*36*4=29952)
#define BBUF     (K_*SA_*2)                 // 12800
#define B_OFF    ABYTES                     // 83200
#define V_OFF    (B_OFF + 2*BBUF)           // 108800
#define RINV_OFF (V_OFF + 2*K_*D_*4)        // 125184
#define MK_OFF   (RINV_OFF + MR_*4)         // 126016
#define CA_OFF   (MK_OFF + 256)             // 126272
#define TA_OFF   (CA_OFF + 128)             // 126400
#define TB_OFF   (TA_OFF + 128)             // 126528
#define SMEM_ATTN (TB_OFF + 128)            // 126656

// -------- scratch (device globals: no allocations allowed) --------
__device__ float g_query[I_*H_*Q_*D_];   // (i,h,q,d)
__device__ float g_key  [T_*H_*K_*D_];   // (t,h,k,d)
__device__ float g_value[T_*H_*K_*D_];   // (t,h,k,d)
__device__ float g_pooled[I_*T_*E_];     // (i*T+t, e)
__device__ float g_maskf[T_*K_];

// -------- PTX helpers (sm_80-class, safe on plain sm_103 target) --------
__device__ __forceinline__ unsigned smem_u32(const void* p) {
    unsigned a;
    asm("{ .reg .u64 t; cvta.to.shared.u64 t, %1; cvt.u32.u64 %0, t; }" : "=r"(a) : "l"(p));
    return a;
}
__device__ __forceinline__ void ldm_x4(unsigned addr, unsigned& r0, unsigned& r1,
                                       unsigned& r2, unsigned& r3) {
    asm volatile("ldmatrix.sync.aligned.m8n8.x4.shared.b16 {%0,%1,%2,%3}, [%4];"
                 : "=r"(r0), "=r"(r1), "=r"(r2), "=r"(r3) : "r"(addr));
}
// NON-trans x2: from token-major rows this yields exactly the mma B fragment
// (lane l -> [token l/4][feature (l%4)*2]), per the PTX m16n8k16 B layout.
__device__ __forceinline__ void ldm_x2(unsigned addr, unsigned& r0, unsigned& r1) {
    asm volatile("ldmatrix.sync.aligned.m8n8.x2.shared.b16 {%0,%1}, [%2];"
                 : "=r"(r0), "=r"(r1) : "r"(addr));
}
__device__ __forceinline__ void mma_bf16(float* c, unsigned a0, unsigned a1, unsigned a2,
                                         unsigned a3, unsigned b0, unsigned b1) {
    asm volatile("mma.sync.aligned.m16n8k16.row.col.f32.bf16.bf16.f32 "
                 "{%0,%1,%2,%3}, {%4,%5,%6,%7}, {%8,%9}, {%0,%1,%2,%3};"
                 : "+f"(c[0]), "+f"(c[1]), "+f"(c[2]), "+f"(c[3])
                 : "r"(a0), "r"(a1), "r"(a2), "r"(a3), "r"(b0), "r"(b1));
}

// -------- mask conversion (robust to bool/int32/float32 serialization) --------
__global__ void mask_kernel(const void* mp) {
    __shared__ int mode;
    if (threadIdx.x == 0) {
        const unsigned char* b = (const unsigned char*)mp;
        int c3f = 0, cnz = 0;
        for (int k = 0; k < 512; k++) {
            if (b[4*k+3] == 0x3F) c3f++;
            if (b[4*k+1] | b[4*k+2]) cnz++;
        }
        mode = (c3f > 8) ? 2 : ((cnz > 8) ? 0 : 1);
    }
    __syncthreads();
    int m = mode;
    for (int idx = threadIdx.x; idx < T_*K_; idx += blockDim.x) {
        float v;
        if (m == 0)      v = ((const unsigned char*)mp)[idx] ? 1.f : 0.f;
        else if (m == 1) v = ((const int*)mp)[idx] ? 1.f : 0.f;
        else             v = (((const float*)mp)[idx] != 0.f) ? 1.f : 0.f;
        g_maskf[idx] = v;
    }
}

// -------- fused Q/K/V projections, one launch (904 CTAs) --------
__global__ void proj_all(const float* __restrict__ image, const float* __restrict__ text,
                         const float* __restrict__ Wq, const float* __restrict__ Wk,
                         const float* __restrict__ Wv) {
    __shared__ float sA[64*33];
    __shared__ float sB[64*33];
    int bid = blockIdx.x;
    int which, h, rb;
    const float *X, *W;
    float* Y;
    if (bid < 392)      { which = 0; h = bid/49;        rb = bid%49;        X = image; W = Wq; Y = g_query; }
    else if (bid < 648) { which = 1; h = (bid-392)/32;  rb = (bid-392)%32;  X = text;  W = Wk; Y = g_key;   }
    else                { which = 2; h = (bid-648)/32;  rb = (bid-648)%32;  X = text;  W = Wv; Y = g_value; }
    int r0 = rb * 64;
    int tid = threadIdx.x;
    int tx = tid & 15, ty = tid >> 4;
    float acc[4][4] = {};

    #pragma unroll
    for (int kc = 0; kc < 64; kc += 32) {
        for (int idx = tid; idx < 2048; idx += 256) {
            int r = idx >> 5, kk = idx & 31;
            sA[r*33 + kk] = X[(r0 + r)*E_ + h*64 + kc + kk];
            sB[r*33 + kk] = W[r*64 + kc + kk];
        }
        __syncthreads();
        #pragma unroll
        for (int kk = 0; kk < 32; kk++) {
            float a[4], b[4];
            #pragma unroll
            for (int r = 0; r < 4; r++) a[r] = sA[(ty*4 + r)*33 + kk];
            #pragma unroll
            for (int c = 0; c < 4; c++) b[c] = sB[(tx*4 + c)*33 + kk];
            #pragma unroll
            for (int r = 0; r < 4; r++)
                #pragma unroll
                for (int c = 0; c < 4; c++) acc[r][c] += a[r] * b[c];
        }
        __syncthreads();
    }
    #pragma unroll
    for (int r = 0; r < 4; r++) {
        int row = r0 + ty*4 + r;
        long long obase;
        if (which == 0) { int i = row / Q_, q = row % Q_;  obase = ((long long)(i*H_ + h)*Q_ + q)*64; }
        else            { int t = row >> 5, k = row & 31;  obase = ((long long)(t*H_ + h)*K_ + k)*64; }
        #pragma unroll
        for (int c = 0; c < 4; c++)
            Y[obase + tx*4 + c] = acc[r][c];
    }
}

// -------- fused warp-MMA energy + dual softmax + pooled-AV --------
// grid 128 (= i*8 + h), 256 threads, occ 1. Split bf16: A=[hi|hi|lo], B=[hi|lo|hi], K=192.
__global__ void __launch_bounds__(256, 1)
attn_kernel(float* __restrict__ out, int wAttn, int wText) {
    extern __shared__ unsigned char smem[];
    unsigned sbase = smem_u32(smem);
    float* sE    = (float*)smem;                    // overlaps A region (A consumed into regs)
    float* sV    = (float*)(smem + V_OFF);
    float* sRinv = (float*)(smem + RINV_OFF);
    float* sMkA  = (float*)(smem + MK_OFF);
    float* sCA   = (float*)(smem + CA_OFF);
    float* sTA   = (float*)(smem + TA_OFF);
    float* sTB   = (float*)(smem + TB_OFF);

    int ih = blockIdx.x;
    int h = ih & 7, i = ih >> 3;
    int tid = threadIdx.x, lane = tid & 31, wid = tid >> 5;

    // ---- stage A (Q tile) as bf16 split into padded smem ----
    {
        unsigned* z = (unsigned*)smem;
        for (int idx = tid; idx < (MR_*SA_)/2; idx += 256) z[idx] = 0u;
        __syncthreads();
        const float* Qg = g_query + (size_t)ih*(Q_*D_);
        __nv_bfloat16* A = (__nv_bfloat16*)smem;
        for (int idx = tid; idx < Q_*D_; idx += 256) {
            int q = idx >> 6, d = idx & 63;
            float x = Qg[idx];
            __nv_bfloat16 hi = __float2bfloat16(x);
            __nv_bfloat16 lo = __float2bfloat16(x - __bfloat162float(hi));
            A[q*SA_ + d]       = hi;
            A[q*SA_ + 64 + d]  = hi;
            A[q*SA_ + 128 + d] = lo;
        }
        __syncthreads();
    }

    // ---- hoist A fragments into registers (reused for all 64 t-tiles) ----
    unsigned af[2][12][4];
    bool has2 = (wid + 8) < 13;
    {
        int lrow = lane & 15;
        int lcol = (lane < 16) ? 0 : 8;
        #pragma unroll
        for (int wti = 0; wti < 2; wti++) {
            int wt = wid + wti*8;
            if (wti == 0 || has2) {
                #pragma unroll
                for (int ks = 0; ks < 12; ks++) {
                    unsigned addr = sbase + (unsigned)(((wt*16 + lrow)*SA_ + ks*16 + lcol)*2);
                    ldm_x4(addr, af[wti][ks][0], af[wti][ks][1], af[wti][ks][2], af[wti][ks][3]);
                }
            }
        }
    }

    // ---- stage t=0 K/V/mask into buffer 0 ----
    {
        const float* Kg = g_key + (size_t)(0*H_ + h)*(K_*D_);
        __nv_bfloat16* B = (__nv_bfloat16*)(smem + B_OFF);
        for (int idx = tid; idx < K_*D_; idx += 256) {
            int k = idx >> 6, d = idx & 63;
            float x = Kg[idx];
            __nv_bfloat16 hi = __float2bfloat16(x);
            __nv_bfloat16 lo = __float2bfloat16(x - __bfloat162float(hi));
            B[k*SA_ + d] = hi; B[k*SA_ + 64 + d] = lo; B[k*SA_ + 128 + d] = hi;
        }
        const float4* vs = (const float4*)(g_value + (size_t)(0*H_ + h)*(K_*D_));
        float4* vd = (float4*)sV;
        for (int idx = tid; idx < (K_*D_)/4; idx += 256) vd[idx] = vs[idx];
        if (tid < K_) sMkA[tid] = g_maskf[0*K_ + tid];
    }
    __syncthreads();

    int p = 0;
    for (int t = 0; t < T_; t++) {
        // ---- MMA phase: energy for tile t into sE (row-major, stride 36) ----
        {
            unsigned sBb = sbase + B_OFF + (unsigned)(p*BBUF);
            int ln = lane & 15;
            int bn = ln & 7;
            int bc = (ln < 8) ? 0 : 8;
            float c[2][4][4];
            #pragma unroll
            for (int a = 0; a < 2; a++)
                #pragma unroll
                for (int nt = 0; nt < 4; nt++)
                    #pragma unroll
                    for (int r = 0; r < 4; r++) c[a][nt][r] = 0.f;
            #pragma unroll
            for (int ks = 0; ks < 12; ks++) {
                unsigned b0[4], b1[4];
                #pragma unroll
                for (int nt = 0; nt < 4; nt++) {
                    unsigned addr = sBb + (unsigned)(((nt*8 + bn)*SA_ + ks*16 + bc)*2);
                    ldm_x2(addr, b0[nt], b1[nt]);
                }
                #pragma unroll
                for (int nt = 0; nt < 4; nt++) {
                    mma_bf16(c[0][nt], af[0][ks][0], af[0][ks][1], af[0][ks][2], af[0][ks][3],
                             b0[nt], b1[nt]);
                    if (has2)
                        mma_bf16(c[1][nt], af[1][ks][0], af[1][ks][1], af[1][ks][2], af[1][ks][3],
                                 b0[nt], b1[nt]);
                }
            }
            int g = lane >> 2, q2 = lane & 3;
            #pragma unroll
            for (int wti = 0; wti < 2; wti++) {
                if (wti == 1 && !has2) break;
                int r0 = (wid + wti*8)*16 + g;
                #pragma unroll
                for (int nt = 0; nt < 4; nt++) {
                    int col = nt*8 + 2*q2;
                    *(float2*)&sE[r0*EST_ + col]       = make_float2(c[wti][nt][0], c[wti][nt][1]);
                    *(float2*)&sE[(r0 + 8)*EST_ + col] = make_float2(c[wti][nt][2], c[wti][nt][3]);
                }
            }
        }

        // ---- prefetch tile t+1 into other buffers (overlaps tensor execution) ----
        if (t + 1 < T_) {
            int pn = p ^ 1;
            const float* Kg = g_key + (size_t)((t+1)*H_ + h)*(K_*D_);
            __nv_bfloat16* B = (__nv_bfloat16*)(smem + B_OFF + pn*BBUF);
            for (int idx = tid; idx < K_*D_; idx += 256) {
                int k = idx >> 6, d = idx & 63;
                float x = Kg[idx];
                __nv_bfloat16 hi = __float2bfloat16(x);
                __nv_bfloat16 lo = __float2bfloat16(x - __bfloat162float(hi));
                B[k*SA_ + d] = hi; B[k*SA_ + 64 + d] = lo; B[k*SA_ + 128 + d] = hi;
            }
            const float4* vs = (const float4*)(g_value + (size_t)((t+1)*H_ + h)*(K_*D_));
            float4* vd = (float4*)(sV + pn*(K_*D_));
            for (int idx = tid; idx < (K_*D_)/4; idx += 256) vd[idx] = vs[idx];
            if (tid < K_) sMkA[pn*32 + tid] = g_maskf[(t+1)*K_ + tid];
        }
        __syncthreads();

        const float* mk = sMkA + p*32;

        // ---- exp + row sums (thread owns q-row; conflict-free float4) ----
        if (tid < Q_) {
            float4* row = (float4*)(sE + tid*EST_);
            float rowsum = 0.f;
            #pragma unroll
            for (int j = 0; j < 8; j++) {
                float4 v = row[j];
                v.x = (mk[4*j + 0] != 0.f) ? exp2f(v.x * SC2_) : 0.f;
                v.y = (mk[4*j + 1] != 0.f) ? exp2f(v.y * SC2_) : 0.f;
                v.z = (mk[4*j + 2] != 0.f) ? exp2f(v.z * SC2_) : 0.f;
                v.w = (mk[4*j + 3] != 0.f) ? exp2f(v.w * SC2_) : 0.f;
                rowsum += (v.x + v.y) + (v.z + v.w);
                row[j] = v;
            }
            sRinv[tid] = 1.f / rowsum;
        }
        __syncthreads();

        // ---- column sums (8 threads per k, conflict-free) ----
        {
            int kcol = tid >> 3, qoff = tid & 7;
            float pe = 0.f, pa = 0.f;
            for (int q = qoff; q < Q_; q += 8) {
                float ee = sE[q*EST_ + kcol];
                pe += ee; pa += ee * sRinv[q];
            }
            #pragma unroll
            for (int o = 4; o > 0; o >>= 1) {
                pe += __shfl_xor_sync(0xffffffffu, pe, o);
                pa += __shfl_xor_sync(0xffffffffu, pa, o);
            }
            if (qoff == 0) {
                float m = mk[kcol];
                sCA[kcol] = pa;
                sTA[kcol] = (m != 0.f) ? (1.f / pe) : 0.f;
                sTB[kcol] = (m != 0.f) ? 0.f : (1.f / (float)Q_);
            }
        }
        __syncthreads();

        // ---- writeout (STG.128 only) + pooled ----
        long long tileOff = ((long long)(i*T_ + t)*H_ + h) * (Q_*K_);
        if (wAttn | wText) {
            float4* attn4 = (float4*)(out + OUT_N + tileOff);
            float4* text4 = (float4*)(out + OUT_N + (long long)ATT_N + tileOff);
            const float4* sE4 = (const float4*)sE;
            const float4* tA4 = (const float4*)sTA;
            const float4* tB4 = (const float4*)sTB;
            for (int idx = tid; idx < Q_*8; idx += 256) {
                int q = idx >> 3, c = idx & 7;
                float4 e4 = sE4[q*(EST_/4) + c];
                if (wAttn) {
                    float r = sRinv[q];
                    float4 a4 = { e4.x*r, e4.y*r, e4.z*r, e4.w*r };
                    attn4[idx] = a4;
                }
                if (wText) {
                    float4 ta = tA4[c], tb = tB4[c];
                    float4 x4 = { fmaf(e4.x, ta.x, tb.x), fmaf(e4.y, ta.y, tb.y),
                                  fmaf(e4.z, ta.z, tb.z), fmaf(e4.w, ta.w, tb.w) };
                    text4[idx] = x4;
                }
            }
        }
        if (tid < 64) {
            float a = 0.f;
            const float* vv = sV + p*(K_*D_);
            #pragma unroll
            for (int k = 0; k < 32; k++) a += sCA[k] * vv[k*D_ + tid];
            g_pooled[(long long)(i*T_ + t)*E_ + h*64 + tid] = a * (1.f / (float)Q_);
        }
        __syncthreads();
        p ^= 1;
    }
}

// -------- final: out[row,f] = sum_e pooled[row,e]*Wo[f,e] + bo[f] --------
__global__ void fc_kernel(const float* __restrict__ Wo, const float* __restrict__ bo,
                          float* __restrict__ out) {
    __shared__ float sA[64*33];
    __shared__ float sB[64*33];
    int rt = blockIdx.x * 64;
    int ct = blockIdx.y * 64;
    int tid = threadIdx.x;
    int tx = tid & 15, ty = tid >> 4;
    float acc[4][4] = {};

    for (int kc = 0; kc < E_; kc += 32) {
        for (int idx = tid; idx < 2048; idx += 256) {
            int r = idx >> 5, kk = idx & 31;
            sA[r*33 + kk] = g_pooled[(rt + r)*E_ + kc + kk];
            sB[r*33 + kk] = Wo[(ct + r)*E_ + kc + kk];
        }
        __syncthreads();
        #pragma unroll
        for (int kk = 0; kk < 32; kk++) {
            float a[4], b[4];
            #pragma unroll
            for (int r = 0; r < 4; r++) a[r] = sA[(ty*4 + r)*33 + kk];
            #pragma unroll
            for (int c = 0; c < 4; c++) b[c] = sB[(tx*4 + c)*33 + kk];
            #pragma unroll
            for (int r = 0; r < 4; r++)
                #pragma unroll
                for (int c = 0; c < 4; c++) acc[r][c] += a[r] * b[c];
        }
        __syncthreads();
    }
    #pragma unroll
    for (int r = 0; r < 4; r++)
        #pragma unroll
        for (int c = 0; c < 4; c++)
            out[(rt + ty*4 + r)*E_ + ct + tx*4 + c] = acc[r][c] + bo[ct + tx*4 + c];
}

// -------- launch --------
extern "C" void kernel_launch(void* const* d_in, const int* in_sizes, int n_in,
                              void* d_out, int out_size) {
    const float* image = (const float*)d_in[0];
    const float* text  = (const float*)d_in[1];
    const void*  mask  =                d_in[2];
    const float* Wq    = (const float*)d_in[3];
    const float* Wk    = (const float*)d_in[4];
    const float* Wv    = (const float*)d_in[5];
    const float* Wo    = (const float*)d_in[6];
    const float* bo    = (const float*)d_in[7];
    float* out = (float*)d_out;

    cudaFuncSetAttribute(attn_kernel, cudaFuncAttributeMaxDynamicSharedMemorySize, SMEM_ATTN);

    mask_kernel<<<1, 256>>>(mask);
    proj_all<<<904, 256>>>(image, text, Wq, Wk, Wv);

    int wAttn = out_size >= (OUT_N + ATT_N);
    int wText = out_size >= (OUT_N + 2*ATT_N);
    attn_kernel<<<I_*H_, 256, SMEM_ATTN>>>(out, wAttn, wText);

    if (out_size >= OUT_N)
        fc_kernel<<<dim3(16, 8), 256>>>(Wo, bo, out);
}